// round 6
// baseline (speedup 1.0000x reference)
#include <cuda_runtime.h>
#include <cuda_bf16.h>
#include <math.h>
#include <stdint.h>

// ---------------------------------------------------------------------------
// Problem constants
// ---------------------------------------------------------------------------
#define N_NODES 50000
#define N_EDGES 10000
#define NNZ     400000
#define QDIM    128
#define VDIM    256
#define EDIM    256
#define KIN     256
#define KP      128          // K/2 pairs (all GEMMs have K=256)
#define NEG_SLOPE 0.01f
#define SCORE_SCALE 0.08838834764831845f   // 1/sqrt(128)

// ---------------------------------------------------------------------------
// Static scratch (no allocation allowed)
// ---------------------------------------------------------------------------
__device__ uint2 g_vfeat_pk[N_NODES * KP];    // packed hi/lo vfeat
__device__ uint2 g_efeat_pk[N_EDGES * KP];
__device__ uint2 g_featv_pk[N_NODES * KP];    // packed feat_v (GEMM-only consumer)
__device__ uint2 g_feate_pk[N_EDGES * KP];
__device__ uint2 g_W_pk[7][256 * KP];         // packed weights (slot-major)
__device__ float g_k1[N_NODES * QDIM];
__device__ float g_v1[N_NODES * EDIM];
__device__ float g_q2[N_NODES * QDIM];
__device__ float g_q1[N_EDGES * QDIM];
__device__ float g_k2[N_EDGES * QDIM];
__device__ float g_v2[N_EDGES * VDIM];
__device__ float g_score[NNZ];
__device__ float g_expw[NNZ];
__device__ float g_segmax[N_NODES];
__device__ float g_segsum[N_NODES];
__device__ int   g_counts[N_NODES];
__device__ int   g_offsets[N_NODES + 1];
__device__ int   g_cursor[N_NODES];
__device__ int   g_perm[NNZ];
__device__ int   g_partials[64];

// ---------------------------------------------------------------------------
// hi/lo bf16 split helpers
// ---------------------------------------------------------------------------
__device__ __forceinline__ uint2 split2(float x0, float x1)
{
    __nv_bfloat16 h0 = __float2bfloat16_rn(x0);
    __nv_bfloat16 h1 = __float2bfloat16_rn(x1);
    __nv_bfloat16 l0 = __float2bfloat16_rn(x0 - __bfloat162float(h0));
    __nv_bfloat16 l1 = __float2bfloat16_rn(x1 - __bfloat162float(h1));
    uint2 r;
    r.x = (uint32_t)__bfloat16_as_ushort(h0) | ((uint32_t)__bfloat16_as_ushort(h1) << 16);
    r.y = (uint32_t)__bfloat16_as_ushort(l0) | ((uint32_t)__bfloat16_as_ushort(l1) << 16);
    return r;
}

// split fp32 matrix -> packed pairs; processes 4 floats (2 pairs) per thread
__global__ void split_kernel(const float* __restrict__ X, uint2* __restrict__ P, int nquads)
{
    int i = blockIdx.x * blockDim.x + threadIdx.x;
    if (i < nquads) {
        float4 f = ((const float4*)X)[i];
        uint2 p0 = split2(f.x, f.y);
        uint2 p1 = split2(f.z, f.w);
        ((uint4*)P)[i] = make_uint4(p0.x, p0.y, p1.x, p1.y);
    }
}

// ---------------------------------------------------------------------------
// bf16-split tensor-core GEMM on pre-packed operands.
// C[M,N] = A[M,K] @ W[N,K]^T + bias[N], computed as hh + hl + lh.
// Block 128x64, BK=32, 256 threads = 8 warps (4m x 2n), warp tile 32x32.
// Staging is pure LDG.128 -> STS.128 (no arithmetic).
// ---------------------------------------------------------------------------
#define BM 128
#define BN 64
#define BK 32
#define SS2 20   // row stride in uint2 units (conflict-free)

__device__ __forceinline__ void mma_bf16(float* c,
    uint32_t a0, uint32_t a1, uint32_t a2, uint32_t a3,
    uint32_t b0, uint32_t b1)
{
    asm volatile(
        "mma.sync.aligned.m16n8k16.row.col.f32.bf16.bf16.f32 "
        "{%0,%1,%2,%3}, {%4,%5,%6,%7}, {%8,%9}, {%0,%1,%2,%3};"
        : "+f"(c[0]), "+f"(c[1]), "+f"(c[2]), "+f"(c[3])
        : "r"(a0), "r"(a1), "r"(a2), "r"(a3), "r"(b0), "r"(b1));
}

template <bool PACK_OUT>
__global__ __launch_bounds__(256, 2) void gemm_pk_kernel(
    const uint2* __restrict__ Apk, const uint2* __restrict__ Wpk,
    const float* __restrict__ bias, float* __restrict__ Cf,
    uint2* __restrict__ Cpk, int M, int N, int K)
{
    __shared__ uint2 As2[BM][SS2];
    __shared__ uint2 Bs2[BN][SS2];

    const int t    = threadIdx.x;
    const int lane = t & 31;
    const int wid  = t >> 5;
    const int wm   = wid & 3;
    const int wn   = wid >> 2;
    const int g    = lane >> 2;
    const int t4   = lane & 3;

    const int block_m = blockIdx.y * BM;
    const int block_n = blockIdx.x * BN;
    const int kp = K >> 1;

    // staging: A: 2 threads/row, 8 uint2 (64B) each; B: 4 threads/row, 4 uint2 (32B)
    const int arow_i = t >> 1;
    const int aseg   = (t & 1) * 8;
    const int brow_i = t >> 2;
    const int bseg   = (t & 3) * 4;
    const int gma = block_m + arow_i;
    const uint2* aptr = Apk + (size_t)(gma < M ? gma : (M - 1)) * kp + aseg;
    const uint2* bptr = Wpk + (size_t)(block_n + brow_i) * kp + bseg;

    float acc[2][4][4];
#pragma unroll
    for (int i = 0; i < 2; i++)
#pragma unroll
        for (int j = 0; j < 4; j++)
#pragma unroll
            for (int l = 0; l < 4; l++) acc[i][j][l] = 0.f;

    uint4 pa[4], pb[2];
#pragma unroll
    for (int u = 0; u < 4; u++) pa[u] = *(const uint4*)(aptr + u * 2);
#pragma unroll
    for (int u = 0; u < 2; u++) pb[u] = *(const uint4*)(bptr + u * 2);

    const int NC = K / BK;
    for (int c = 0; c < NC; c++) {
        // ---- stage current chunk (pure copy) ----
#pragma unroll
        for (int u = 0; u < 4; u++)
            *(uint4*)&As2[arow_i][aseg + u * 2] = pa[u];
#pragma unroll
        for (int u = 0; u < 2; u++)
            *(uint4*)&Bs2[brow_i][bseg + u * 2] = pb[u];
        __syncthreads();

        // ---- prefetch next chunk ----
        if (c + 1 < NC) {
            const int o = (c + 1) * (BK / 2);
#pragma unroll
            for (int u = 0; u < 4; u++) pa[u] = *(const uint4*)(aptr + o + u * 2);
#pragma unroll
            for (int u = 0; u < 2; u++) pb[u] = *(const uint4*)(bptr + o + u * 2);
        }

        // ---- 2 k16-steps ----
#pragma unroll
        for (int kk = 0; kk < 2; kk++) {
            const int kc0 = kk * 8 + t4;
            const int kc1 = kc0 + 4;
            uint32_t ahi[2][4], alo[2][4];
#pragma unroll
            for (int mt = 0; mt < 2; mt++) {
                const int r0 = wm * 32 + mt * 16 + g;
                uint2 v0 = As2[r0][kc0];
                uint2 v1 = As2[r0 + 8][kc0];
                uint2 v2 = As2[r0][kc1];
                uint2 v3 = As2[r0 + 8][kc1];
                ahi[mt][0] = v0.x; alo[mt][0] = v0.y;
                ahi[mt][1] = v1.x; alo[mt][1] = v1.y;
                ahi[mt][2] = v2.x; alo[mt][2] = v2.y;
                ahi[mt][3] = v3.x; alo[mt][3] = v3.y;
            }
            uint32_t bhi[4][2], blo[4][2];
#pragma unroll
            for (int nt = 0; nt < 4; nt++) {
                const int n0 = wn * 32 + nt * 8 + g;
                uint2 u0 = Bs2[n0][kc0];
                uint2 u1 = Bs2[n0][kc1];
                bhi[nt][0] = u0.x; blo[nt][0] = u0.y;
                bhi[nt][1] = u1.x; blo[nt][1] = u1.y;
            }
#pragma unroll
            for (int mt = 0; mt < 2; mt++)
#pragma unroll
                for (int nt = 0; nt < 4; nt++)
                    mma_bf16(acc[mt][nt], ahi[mt][0], ahi[mt][1], ahi[mt][2], ahi[mt][3],
                             bhi[nt][0], bhi[nt][1]);
#pragma unroll
            for (int mt = 0; mt < 2; mt++)
#pragma unroll
                for (int nt = 0; nt < 4; nt++)
                    mma_bf16(acc[mt][nt], ahi[mt][0], ahi[mt][1], ahi[mt][2], ahi[mt][3],
                             blo[nt][0], blo[nt][1]);
#pragma unroll
            for (int mt = 0; mt < 2; mt++)
#pragma unroll
                for (int nt = 0; nt < 4; nt++)
                    mma_bf16(acc[mt][nt], alo[mt][0], alo[mt][1], alo[mt][2], alo[mt][3],
                             bhi[nt][0], bhi[nt][1]);
        }
        __syncthreads();
    }

    // ---- epilogue ----
#pragma unroll
    for (int mt = 0; mt < 2; mt++) {
#pragma unroll
        for (int nt = 0; nt < 4; nt++) {
            const int m0 = block_m + wm * 32 + mt * 16 + g;
            const int n0 = block_n + wn * 32 + nt * 8 + t4 * 2;
            const float bv0 = bias[n0], bv1 = bias[n0 + 1];
            if (PACK_OUT) {
                const int pcol = n0 >> 1;
                if (m0 < M)
                    Cpk[(size_t)m0 * (N >> 1) + pcol] =
                        split2(acc[mt][nt][0] + bv0, acc[mt][nt][1] + bv1);
                if (m0 + 8 < M)
                    Cpk[(size_t)(m0 + 8) * (N >> 1) + pcol] =
                        split2(acc[mt][nt][2] + bv0, acc[mt][nt][3] + bv1);
            } else {
                if (m0 < M) {
                    float2 o = make_float2(acc[mt][nt][0] + bv0, acc[mt][nt][1] + bv1);
                    *(float2*)&Cf[(size_t)m0 * N + n0] = o;
                }
                if (m0 + 8 < M) {
                    float2 o = make_float2(acc[mt][nt][2] + bv0, acc[mt][nt][3] + bv1);
                    *(float2*)&Cf[(size_t)(m0 + 8) * N + n0] = o;
                }
            }
        }
    }
}

static void run_gemm_f(const uint2* Apk, const uint2* Wpk, const float* b, float* C,
                       int M, int N, int K)
{
    dim3 grid(N / BN, (M + BM - 1) / BM);
    gemm_pk_kernel<false><<<grid, 256>>>(Apk, Wpk, b, C, nullptr, M, N, K);
}
static void run_gemm_pk(const uint2* Apk, const uint2* Wpk, const float* b, uint2* Cpk,
                        int M, int N, int K)
{
    dim3 grid(N / BN, (M + BM - 1) / BM);
    gemm_pk_kernel<true><<<grid, 256>>>(Apk, Wpk, b, nullptr, Cpk, M, N, K);
}

// ---------------------------------------------------------------------------
// Softmax / segment machinery (unchanged)
// ---------------------------------------------------------------------------
__device__ __forceinline__ void atomicMaxFloat(float* addr, float val)
{
    if (val >= 0.f)
        atomicMax((int*)addr, __float_as_int(val));
    else
        atomicMin((unsigned int*)addr, __float_as_uint(val));
}

__global__ void init_pass_kernel(float* segmax, float* segsum, int* counts, int nseg)
{
    int i = blockIdx.x * blockDim.x + threadIdx.x;
    if (i < nseg) {
        segmax[i] = -INFINITY;
        segsum[i] = 0.f;
        counts[i] = 0;
    }
}

__global__ __launch_bounds__(256) void score_kernel(
    const float* __restrict__ kmat, const float* __restrict__ qmat,
    const int* __restrict__ kidx, const int* __restrict__ qidx,
    const int* __restrict__ seg,
    float* __restrict__ score, float* __restrict__ segmax, int* __restrict__ counts,
    int nnz)
{
    const int w = (blockIdx.x * blockDim.x + threadIdx.x) >> 5;
    const int lane = threadIdx.x & 31;
    if (w >= nnz) return;
    const int ki = kidx[w];
    const int qi = qidx[w];
    float4 a = *(const float4*)&kmat[(size_t)ki * QDIM + lane * 4];
    float4 b = *(const float4*)&qmat[(size_t)qi * QDIM + lane * 4];
    float d = a.x * b.x + a.y * b.y + a.z * b.z + a.w * b.w;
#pragma unroll
    for (int o = 16; o > 0; o >>= 1) d += __shfl_xor_sync(0xffffffffu, d, o);
    if (lane == 0) {
        float s = (d >= 0.f ? d : NEG_SLOPE * d) * SCORE_SCALE;
        score[w] = s;
        const int sg = seg[w];
        atomicMaxFloat(&segmax[sg], s);
        atomicAdd(&counts[sg], 1);
    }
}

__global__ __launch_bounds__(1024) void scan_block_kernel(
    const int* __restrict__ counts, int* __restrict__ offsets,
    int* __restrict__ partials, int n)
{
    __shared__ int sh[1024];
    const int t = threadIdx.x;
    const int i = blockIdx.x * 1024 + t;
    const int x = (i < n) ? counts[i] : 0;
    sh[t] = x;
    __syncthreads();
    for (int off = 1; off < 1024; off <<= 1) {
        int v = (t >= off) ? sh[t - off] : 0;
        __syncthreads();
        sh[t] += v;
        __syncthreads();
    }
    if (i < n) offsets[i] = sh[t] - x;
    if (t == 1023) partials[blockIdx.x] = sh[1023];
}

__global__ void scan_partials_kernel(int* partials, int* offsets, int nb, int n)
{
    __shared__ int sh[64];
    const int t = threadIdx.x;
    const int x = (t < nb) ? partials[t] : 0;
    sh[t] = x;
    __syncthreads();
    for (int off = 1; off < 64; off <<= 1) {
        int v = (t >= off) ? sh[t - off] : 0;
        __syncthreads();
        sh[t] += v;
        __syncthreads();
    }
    if (t < nb) partials[t] = sh[t] - x;
    if (t == 63) offsets[n] = sh[63];
}

__global__ void scan_add_kernel(int* __restrict__ offsets, int* __restrict__ cursor,
                                const int* __restrict__ partials, int n)
{
    int i = blockIdx.x * blockDim.x + threadIdx.x;
    if (i < n) {
        int v = offsets[i] + partials[i >> 10];
        offsets[i] = v;
        cursor[i] = v;
    }
}

__global__ void build_perm_kernel(const int* __restrict__ seg, int* __restrict__ cursor,
                                  int* __restrict__ perm, int nnz)
{
    int i = blockIdx.x * blockDim.x + threadIdx.x;
    if (i < nnz) {
        int pos = atomicAdd(&cursor[seg[i]], 1);
        perm[pos] = i;
    }
}

__global__ void expsum_kernel(const float* __restrict__ score, const int* __restrict__ seg,
                              const float* __restrict__ segmax, float* __restrict__ expw,
                              float* __restrict__ segsum, int nnz)
{
    int i = blockIdx.x * blockDim.x + threadIdx.x;
    if (i < nnz) {
        const int sg = seg[i];
        float e = expf(score[i] - segmax[sg]);
        expw[i] = e;
        atomicAdd(&segsum[sg], e);
    }
}

__global__ __launch_bounds__(256) void aggregate_kernel(
    const float* __restrict__ vmat,
    const int* __restrict__ rowidx,
    const int* __restrict__ offsets, const int* __restrict__ perm,
    const float* __restrict__ expw, const float* __restrict__ segsum,
    float* __restrict__ out, int nseg)
{
    __shared__ int   sh_r[128];
    __shared__ float sh_w[128];
    const int s = blockIdx.x;
    if (s >= nseg) return;
    const int d = threadIdx.x;
    const int beg = offsets[s];
    const int end = offsets[s + 1];
    float acc = 0.f;
    for (int cb = beg; cb < end; cb += 128) {
        const int m = min(128, end - cb);
        if (d < m) {
            const int nz = perm[cb + d];
            sh_w[d] = expw[nz];
            sh_r[d] = rowidx[nz];
        }
        __syncthreads();
        for (int j = 0; j < m; j++)
            acc += sh_w[j] * vmat[(size_t)sh_r[j] * 256 + d];
        __syncthreads();
    }
    const float denom = fmaxf(segsum[s], 1e-20f);
    out[(size_t)s * 256 + d] = fmaxf(acc / denom, 0.f);
}

// ---------------------------------------------------------------------------
// Launch
// ---------------------------------------------------------------------------
extern "C" void kernel_launch(void* const* d_in, const int* in_sizes, int n_in,
                              void* d_out, int out_size)
{
    const float* vfeat    = (const float*)d_in[0];
    const float* efeat    = (const float*)d_in[1];
    const int*   node_idx = (const int*)d_in[2];
    const int*   edge_idx = (const int*)d_in[3];
    const float* W_vtx = (const float*)d_in[4];  const float* b_vtx = (const float*)d_in[5];
    const float* W_qe  = (const float*)d_in[6];  const float* b_qe  = (const float*)d_in[7];
    const float* W_kv  = (const float*)d_in[8];  const float* b_kv  = (const float*)d_in[9];
    const float* W_vv  = (const float*)d_in[10]; const float* b_vv  = (const float*)d_in[11];
    const float* W_qv  = (const float*)d_in[12]; const float* b_qv  = (const float*)d_in[13];
    const float* W_ke  = (const float*)d_in[14]; const float* b_ke  = (const float*)d_in[15];
    const float* W_ve  = (const float*)d_in[16]; const float* b_ve  = (const float*)d_in[17];

    float* out_v = (float*)d_out;
    float* out_e = out_v + (size_t)N_NODES * VDIM;

    uint2 *vfeat_pk, *efeat_pk, *featv_pk, *feate_pk, *wpk;
    float *k1, *v1, *q2, *q1, *k2, *v2, *score, *expw, *segmax, *segsum;
    int *counts, *offsets, *cursor, *perm, *partials;
    cudaGetSymbolAddress((void**)&vfeat_pk, g_vfeat_pk);
    cudaGetSymbolAddress((void**)&efeat_pk, g_efeat_pk);
    cudaGetSymbolAddress((void**)&featv_pk, g_featv_pk);
    cudaGetSymbolAddress((void**)&feate_pk, g_feate_pk);
    cudaGetSymbolAddress((void**)&wpk, g_W_pk);
    cudaGetSymbolAddress((void**)&k1, g_k1);
    cudaGetSymbolAddress((void**)&v1, g_v1);
    cudaGetSymbolAddress((void**)&q2, g_q2);
    cudaGetSymbolAddress((void**)&q1, g_q1);
    cudaGetSymbolAddress((void**)&k2, g_k2);
    cudaGetSymbolAddress((void**)&v2, g_v2);
    cudaGetSymbolAddress((void**)&score, g_score);
    cudaGetSymbolAddress((void**)&expw, g_expw);
    cudaGetSymbolAddress((void**)&segmax, g_segmax);
    cudaGetSymbolAddress((void**)&segsum, g_segsum);
    cudaGetSymbolAddress((void**)&counts, g_counts);
    cudaGetSymbolAddress((void**)&offsets, g_offsets);
    cudaGetSymbolAddress((void**)&cursor, g_cursor);
    cudaGetSymbolAddress((void**)&perm, g_perm);
    cudaGetSymbolAddress((void**)&partials, g_partials);

    uint2* Wvtx_pk = wpk + 0 * 256 * KP;
    uint2* Wqe_pk  = wpk + 1 * 256 * KP;
    uint2* Wkv_pk  = wpk + 2 * 256 * KP;
    uint2* Wvv_pk  = wpk + 3 * 256 * KP;
    uint2* Wqv_pk  = wpk + 4 * 256 * KP;
    uint2* Wke_pk  = wpk + 5 * 256 * KP;
    uint2* Wve_pk  = wpk + 6 * 256 * KP;

    const int scoreBlocks = (NNZ * 32 + 255) / 256;
    const int nnzBlocks   = (NNZ + 255) / 256;

    // ---- one-time operand splits ----
    split_kernel<<<(N_NODES * KIN / 4 + 255) / 256, 256>>>(vfeat, vfeat_pk, N_NODES * KIN / 4);
    split_kernel<<<(N_EDGES * KIN / 4 + 255) / 256, 256>>>(efeat, efeat_pk, N_EDGES * KIN / 4);
    split_kernel<<<(VDIM * KIN / 4 + 255) / 256, 256>>>(W_vtx, Wvtx_pk, VDIM * KIN / 4);
    split_kernel<<<(QDIM * KIN / 4 + 255) / 256, 256>>>(W_qe,  Wqe_pk,  QDIM * KIN / 4);
    split_kernel<<<(QDIM * VDIM / 4 + 255) / 256, 256>>>(W_kv,  Wkv_pk,  QDIM * VDIM / 4);
    split_kernel<<<(EDIM * VDIM / 4 + 255) / 256, 256>>>(W_vv,  Wvv_pk,  EDIM * VDIM / 4);
    split_kernel<<<(QDIM * VDIM / 4 + 255) / 256, 256>>>(W_qv,  Wqv_pk,  QDIM * VDIM / 4);
    split_kernel<<<(QDIM * EDIM / 4 + 255) / 256, 256>>>(W_ke,  Wke_pk,  QDIM * EDIM / 4);
    split_kernel<<<(VDIM * EDIM / 4 + 255) / 256, 256>>>(W_ve,  Wve_pk,  VDIM * EDIM / 4);

    // ---- projections ----
    run_gemm_pk(vfeat_pk, Wvtx_pk, b_vtx, featv_pk, N_NODES, VDIM, KIN);  // feat_v (packed)
    run_gemm_f(featv_pk, Wkv_pk, b_kv, k1, N_NODES, QDIM, VDIM);
    run_gemm_f(featv_pk, Wvv_pk, b_vv, v1, N_NODES, EDIM, VDIM);
    run_gemm_f(featv_pk, Wqv_pk, b_qv, q2, N_NODES, QDIM, VDIM);
    run_gemm_f(efeat_pk, Wqe_pk, b_qe, q1, N_EDGES, QDIM, KIN);

    // ---- pass 1: nodes -> hyperedges ----
    {
        const int nseg = N_EDGES;
        const int nb = (nseg + 1023) / 1024;
        init_pass_kernel<<<(nseg + 255) / 256, 256>>>(segmax, segsum, counts, nseg);
        score_kernel<<<scoreBlocks, 256>>>(k1, q1, node_idx, edge_idx, edge_idx,
                                           score, segmax, counts, NNZ);
        scan_block_kernel<<<nb, 1024>>>(counts, offsets, partials, nseg);
        scan_partials_kernel<<<1, 64>>>(partials, offsets, nb, nseg);
        scan_add_kernel<<<(nseg + 255) / 256, 256>>>(offsets, cursor, partials, nseg);
        build_perm_kernel<<<nnzBlocks, 256>>>(edge_idx, cursor, perm, NNZ);
        expsum_kernel<<<nnzBlocks, 256>>>(score, edge_idx, segmax, expw, segsum, NNZ);
        aggregate_kernel<<<nseg, 256>>>(v1, node_idx, offsets, perm, expw, segsum,
                                        out_e, nseg);
    }

    // ---- packed copy of feat_e + edge-side projections ----
    split_kernel<<<(N_EDGES * EDIM / 4 + 255) / 256, 256>>>(out_e, feate_pk, N_EDGES * EDIM / 4);
    run_gemm_f(feate_pk, Wke_pk, b_ke, k2, N_EDGES, QDIM, EDIM);
    run_gemm_f(feate_pk, Wve_pk, b_ve, v2, N_EDGES, VDIM, EDIM);

    // ---- pass 2: hyperedges -> nodes ----
    {
        const int nseg = N_NODES;
        const int nb = (nseg + 1023) / 1024;
        init_pass_kernel<<<(nseg + 255) / 256, 256>>>(segmax, segsum, counts, nseg);
        score_kernel<<<scoreBlocks, 256>>>(k2, q2, edge_idx, node_idx, node_idx,
                                           score, segmax, counts, NNZ);
        scan_block_kernel<<<nb, 1024>>>(counts, offsets, partials, nseg);
        scan_partials_kernel<<<1, 64>>>(partials, offsets, nb, nseg);
        scan_add_kernel<<<(nseg + 255) / 256, 256>>>(offsets, cursor, partials, nseg);
        build_perm_kernel<<<nnzBlocks, 256>>>(node_idx, cursor, perm, NNZ);
        expsum_kernel<<<nnzBlocks, 256>>>(score, node_idx, segmax, expw, segsum, NNZ);
        aggregate_kernel<<<nseg, 256>>>(v2, edge_idx, offsets, perm, expw, segsum,
                                        out_v, nseg);
    }
}

// round 7
// speedup vs baseline: 1.0045x; 1.0045x over previous
#include <cuda_runtime.h>
#include <cuda_bf16.h>
#include <math.h>
#include <stdint.h>

// ---------------------------------------------------------------------------
// Problem constants
// ---------------------------------------------------------------------------
#define N_NODES 50000
#define N_EDGES 10000
#define NNZ     400000
#define QDIM    128
#define VDIM    256
#define EDIM    256
#define KIN     256
#define KP      128          // K/2 pairs (all GEMMs have K=256)
#define NEG_SLOPE 0.01f
#define SCORE_SCALE 0.08838834764831845f   // 1/sqrt(128)

// ---------------------------------------------------------------------------
// Static scratch (no allocation allowed)
// ---------------------------------------------------------------------------
__device__ uint2 g_vfeat_pk[N_NODES * KP];
__device__ uint2 g_efeat_pk[N_EDGES * KP];
__device__ uint2 g_featv_pk[N_NODES * KP];
__device__ uint2 g_feate_pk[N_EDGES * KP];
__device__ uint2 g_W_pk[7][256 * KP];
__device__ float g_k1[N_NODES * QDIM];
__device__ float g_v1[N_NODES * EDIM];
__device__ float g_q2[N_NODES * QDIM];
__device__ float g_q1[N_EDGES * QDIM];
__device__ float g_k2[N_EDGES * QDIM];
__device__ float g_v2[N_EDGES * VDIM];
__device__ float g_score[NNZ];
__device__ float g_expw[NNZ];
__device__ float g_segmax[N_NODES];
__device__ float g_segsum[N_NODES];
__device__ int   g_counts[N_NODES];
__device__ int   g_offsets[N_NODES + 1];
__device__ int   g_cursor[N_NODES];
__device__ int   g_perm[NNZ];
__device__ int   g_partials[64];

// ---------------------------------------------------------------------------
// hi/lo bf16 split helpers
// ---------------------------------------------------------------------------
__device__ __forceinline__ uint2 split2(float x0, float x1)
{
    __nv_bfloat16 h0 = __float2bfloat16_rn(x0);
    __nv_bfloat16 h1 = __float2bfloat16_rn(x1);
    __nv_bfloat16 l0 = __float2bfloat16_rn(x0 - __bfloat162float(h0));
    __nv_bfloat16 l1 = __float2bfloat16_rn(x1 - __bfloat162float(h1));
    uint2 r;
    r.x = (uint32_t)__bfloat16_as_ushort(h0) | ((uint32_t)__bfloat16_as_ushort(h1) << 16);
    r.y = (uint32_t)__bfloat16_as_ushort(l0) | ((uint32_t)__bfloat16_as_ushort(l1) << 16);
    return r;
}

__global__ void split_kernel(const float* __restrict__ X, uint2* __restrict__ P, int nquads)
{
    int i = blockIdx.x * blockDim.x + threadIdx.x;
    if (i < nquads) {
        float4 f = ((const float4*)X)[i];
        uint2 p0 = split2(f.x, f.y);
        uint2 p1 = split2(f.z, f.w);
        ((uint4*)P)[i] = make_uint4(p0.x, p0.y, p1.x, p1.y);
    }
}

// ---------------------------------------------------------------------------
// bf16-split tensor-core GEMM, cp.async 3-stage pipeline.
// C[M,N] = A[M,K] @ W[N,K]^T + bias[N], computed as hh + hl + lh.
// Block 128x64, BK=32, 256 threads = 8 warps (4m x 2n), warp tile 32x32.
// Dynamic smem: 3 stages x (As 20KB + Bs 10KB) = 90KB -> 2 CTAs/SM.
// ---------------------------------------------------------------------------
#define BM 128
#define BN 64
#define BK 32
#define SS2 20                    // row stride in uint2 units (conflict-free)
#define A_STG (BM * SS2)          // uint2 per A stage
#define B_STG (BN * SS2)
#define SMEM_BYTES (3 * (A_STG + B_STG) * 8)

__device__ __forceinline__ void mma_bf16(float* c,
    uint32_t a0, uint32_t a1, uint32_t a2, uint32_t a3,
    uint32_t b0, uint32_t b1)
{
    asm volatile(
        "mma.sync.aligned.m16n8k16.row.col.f32.bf16.bf16.f32 "
        "{%0,%1,%2,%3}, {%4,%5,%6,%7}, {%8,%9}, {%0,%1,%2,%3};"
        : "+f"(c[0]), "+f"(c[1]), "+f"(c[2]), "+f"(c[3])
        : "r"(a0), "r"(a1), "r"(a2), "r"(a3), "r"(b0), "r"(b1));
}

__device__ __forceinline__ void cp16(uint32_t dst, const void* src)
{
    asm volatile("cp.async.cg.shared.global [%0], [%1], 16;"
                 :: "r"(dst), "l"(src));
}
#define CP_COMMIT() asm volatile("cp.async.commit_group;" ::: "memory")
#define CP_WAIT1()  asm volatile("cp.async.wait_group 1;" ::: "memory")

template <bool PACK_OUT>
__global__ __launch_bounds__(256) void gemm_pk_kernel(
    const uint2* __restrict__ Apk, const uint2* __restrict__ Wpk,
    const float* __restrict__ bias, float* __restrict__ Cf,
    uint2* __restrict__ Cpk, int M, int N, int K)
{
    extern __shared__ uint2 smem[];

    const int t    = threadIdx.x;
    const int lane = t & 31;
    const int wid  = t >> 5;
    const int wm   = wid & 3;
    const int wn   = wid >> 2;
    const int g    = lane >> 2;
    const int t4   = lane & 3;

    const int block_m = blockIdx.y * BM;
    const int block_n = blockIdx.x * BN;
    const int kp = K >> 1;

    // staging: A: 2 threads/row, 8 uint2 (4x cp16); B: 4 threads/row, 4 uint2 (2x cp16)
    const int arow_i = t >> 1;
    const int aseg   = (t & 1) * 8;
    const int brow_i = t >> 2;
    const int bseg   = (t & 3) * 4;
    const int gma = block_m + arow_i;
    const uint2* aptr = Apk + (size_t)(gma < M ? gma : (M - 1)) * kp + aseg;
    const uint2* bptr = Wpk + (size_t)(block_n + brow_i) * kp + bseg;

    const uint32_t smem_base = (uint32_t)__cvta_generic_to_shared(smem);
    const uint32_t a_dst0 = smem_base + (uint32_t)(arow_i * SS2 + aseg) * 8;
    const uint32_t b_dst0 = smem_base + (uint32_t)(3 * A_STG + brow_i * SS2 + bseg) * 8;

    float acc[2][4][4];
#pragma unroll
    for (int i = 0; i < 2; i++)
#pragma unroll
        for (int j = 0; j < 4; j++)
#pragma unroll
            for (int l = 0; l < 4; l++) acc[i][j][l] = 0.f;

    const int NC = K / BK;

    // ---- prologue: stage chunks 0 and 1 ----
#pragma unroll
    for (int p = 0; p < 2; p++) {
        const int ko = p * (BK / 2);
        const uint32_t ad = a_dst0 + (uint32_t)(p * A_STG) * 8;
        const uint32_t bd = b_dst0 + (uint32_t)(p * B_STG) * 8;
#pragma unroll
        for (int u = 0; u < 4; u++) cp16(ad + u * 16, aptr + ko + u * 2);
#pragma unroll
        for (int u = 0; u < 2; u++) cp16(bd + u * 16, bptr + ko + u * 2);
        CP_COMMIT();
    }
    CP_WAIT1();
    __syncthreads();

    for (int c = 0; c < NC; c++) {
        // ---- issue chunk c+2 into slot (c+2)%3 ----
        if (c + 2 < NC) {
            const int s = (c + 2) % 3;
            const int ko = (c + 2) * (BK / 2);
            const uint32_t ad = a_dst0 + (uint32_t)(s * A_STG) * 8;
            const uint32_t bd = b_dst0 + (uint32_t)(s * B_STG) * 8;
#pragma unroll
            for (int u = 0; u < 4; u++) cp16(ad + u * 16, aptr + ko + u * 2);
#pragma unroll
            for (int u = 0; u < 2; u++) cp16(bd + u * 16, bptr + ko + u * 2);
        }
        CP_COMMIT();

        // ---- compute chunk c from slot c%3 ----
        const uint2 (*As2)[SS2] = (const uint2 (*)[SS2])(smem + (c % 3) * A_STG);
        const uint2 (*Bs2)[SS2] = (const uint2 (*)[SS2])(smem + 3 * A_STG + (c % 3) * B_STG);

#pragma unroll
        for (int kk = 0; kk < 2; kk++) {
            const int kc0 = kk * 8 + t4;
            const int kc1 = kc0 + 4;
            uint32_t ahi[2][4], alo[2][4];
#pragma unroll
            for (int mt = 0; mt < 2; mt++) {
                const int r0 = wm * 32 + mt * 16 + g;
                uint2 v0 = As2[r0][kc0];
                uint2 v1 = As2[r0 + 8][kc0];
                uint2 v2 = As2[r0][kc1];
                uint2 v3 = As2[r0 + 8][kc1];
                ahi[mt][0] = v0.x; alo[mt][0] = v0.y;
                ahi[mt][1] = v1.x; alo[mt][1] = v1.y;
                ahi[mt][2] = v2.x; alo[mt][2] = v2.y;
                ahi[mt][3] = v3.x; alo[mt][3] = v3.y;
            }
            uint32_t bhi[4][2], blo[4][2];
#pragma unroll
            for (int nt = 0; nt < 4; nt++) {
                const int n0 = wn * 32 + nt * 8 + g;
                uint2 u0 = Bs2[n0][kc0];
                uint2 u1 = Bs2[n0][kc1];
                bhi[nt][0] = u0.x; blo[nt][0] = u0.y;
                bhi[nt][1] = u1.x; blo[nt][1] = u1.y;
            }
#pragma unroll
            for (int mt = 0; mt < 2; mt++)
#pragma unroll
                for (int nt = 0; nt < 4; nt++)
                    mma_bf16(acc[mt][nt], ahi[mt][0], ahi[mt][1], ahi[mt][2], ahi[mt][3],
                             bhi[nt][0], bhi[nt][1]);
#pragma unroll
            for (int mt = 0; mt < 2; mt++)
#pragma unroll
                for (int nt = 0; nt < 4; nt++)
                    mma_bf16(acc[mt][nt], ahi[mt][0], ahi[mt][1], ahi[mt][2], ahi[mt][3],
                             blo[nt][0], blo[nt][1]);
#pragma unroll
            for (int mt = 0; mt < 2; mt++)
#pragma unroll
                for (int nt = 0; nt < 4; nt++)
                    mma_bf16(acc[mt][nt], alo[mt][0], alo[mt][1], alo[mt][2], alo[mt][3],
                             bhi[nt][0], bhi[nt][1]);
        }

        // ---- chunk c+1 must have landed before next iteration reads it ----
        CP_WAIT1();
        __syncthreads();
    }

    // ---- epilogue ----
#pragma unroll
    for (int mt = 0; mt < 2; mt++) {
#pragma unroll
        for (int nt = 0; nt < 4; nt++) {
            const int m0 = block_m + wm * 32 + mt * 16 + g;
            const int n0 = block_n + wn * 32 + nt * 8 + t4 * 2;
            const float bv0 = bias[n0], bv1 = bias[n0 + 1];
            if (PACK_OUT) {
                const int pcol = n0 >> 1;
                if (m0 < M)
                    Cpk[(size_t)m0 * (N >> 1) + pcol] =
                        split2(acc[mt][nt][0] + bv0, acc[mt][nt][1] + bv1);
                if (m0 + 8 < M)
                    Cpk[(size_t)(m0 + 8) * (N >> 1) + pcol] =
                        split2(acc[mt][nt][2] + bv0, acc[mt][nt][3] + bv1);
            } else {
                if (m0 < M) {
                    float2 o = make_float2(acc[mt][nt][0] + bv0, acc[mt][nt][1] + bv1);
                    *(float2*)&Cf[(size_t)m0 * N + n0] = o;
                }
                if (m0 + 8 < M) {
                    float2 o = make_float2(acc[mt][nt][2] + bv0, acc[mt][nt][3] + bv1);
                    *(float2*)&Cf[(size_t)(m0 + 8) * N + n0] = o;
                }
            }
        }
    }
}

static void run_gemm_f(const uint2* Apk, const uint2* Wpk, const float* b, float* C,
                       int M, int N, int K)
{
    cudaFuncSetAttribute(gemm_pk_kernel<false>,
                         cudaFuncAttributeMaxDynamicSharedMemorySize, SMEM_BYTES);
    dim3 grid(N / BN, (M + BM - 1) / BM);
    gemm_pk_kernel<false><<<grid, 256, SMEM_BYTES>>>(Apk, Wpk, b, C, nullptr, M, N, K);
}
static void run_gemm_pk(const uint2* Apk, const uint2* Wpk, const float* b, uint2* Cpk,
                        int M, int N, int K)
{
    cudaFuncSetAttribute(gemm_pk_kernel<true>,
                         cudaFuncAttributeMaxDynamicSharedMemorySize, SMEM_BYTES);
    dim3 grid(N / BN, (M + BM - 1) / BM);
    gemm_pk_kernel<true><<<grid, 256, SMEM_BYTES>>>(Apk, Wpk, b, nullptr, Cpk, M, N, K);
}

// ---------------------------------------------------------------------------
// Softmax / segment machinery
// ---------------------------------------------------------------------------
__device__ __forceinline__ void atomicMaxFloat(float* addr, float val)
{
    if (val >= 0.f)
        atomicMax((int*)addr, __float_as_int(val));
    else
        atomicMin((unsigned int*)addr, __float_as_uint(val));
}

__global__ void init_pass_kernel(float* segmax, float* segsum, int* counts, int nseg)
{
    int i = blockIdx.x * blockDim.x + threadIdx.x;
    if (i < nseg) {
        segmax[i] = -INFINITY;
        segsum[i] = 0.f;
        counts[i] = 0;
    }
}

__global__ __launch_bounds__(256) void score_kernel(
    const float* __restrict__ kmat, const float* __restrict__ qmat,
    const int* __restrict__ kidx, const int* __restrict__ qidx,
    const int* __restrict__ seg,
    float* __restrict__ score, float* __restrict__ segmax, int* __restrict__ counts,
    int nnz)
{
    const int w = (blockIdx.x * blockDim.x + threadIdx.x) >> 5;
    const int lane = threadIdx.x & 31;
    if (w >= nnz) return;
    const int ki = kidx[w];
    const int qi = qidx[w];
    float4 a = *(const float4*)&kmat[(size_t)ki * QDIM + lane * 4];
    float4 b = *(const float4*)&qmat[(size_t)qi * QDIM + lane * 4];
    float d = a.x * b.x + a.y * b.y + a.z * b.z + a.w * b.w;
#pragma unroll
    for (int o = 16; o > 0; o >>= 1) d += __shfl_xor_sync(0xffffffffu, d, o);
    if (lane == 0) {
        float s = (d >= 0.f ? d : NEG_SLOPE * d) * SCORE_SCALE;
        score[w] = s;
        const int sg = seg[w];
        atomicMaxFloat(&segmax[sg], s);
        atomicAdd(&counts[sg], 1);
    }
}

__global__ __launch_bounds__(1024) void scan_block_kernel(
    const int* __restrict__ counts, int* __restrict__ offsets,
    int* __restrict__ partials, int n)
{
    __shared__ int sh[1024];
    const int t = threadIdx.x;
    const int i = blockIdx.x * 1024 + t;
    const int x = (i < n) ? counts[i] : 0;
    sh[t] = x;
    __syncthreads();
    for (int off = 1; off < 1024; off <<= 1) {
        int v = (t >= off) ? sh[t - off] : 0;
        __syncthreads();
        sh[t] += v;
        __syncthreads();
    }
    if (i < n) offsets[i] = sh[t] - x;
    if (t == 1023) partials[blockIdx.x] = sh[1023];
}

__global__ void scan_partials_kernel(int* partials, int* offsets, int nb, int n)
{
    __shared__ int sh[64];
    const int t = threadIdx.x;
    const int x = (t < nb) ? partials[t] : 0;
    sh[t] = x;
    __syncthreads();
    for (int off = 1; off < 64; off <<= 1) {
        int v = (t >= off) ? sh[t - off] : 0;
        __syncthreads();
        sh[t] += v;
        __syncthreads();
    }
    if (t < nb) partials[t] = sh[t] - x;
    if (t == 63) offsets[n] = sh[63];
}

__global__ void scan_add_kernel(int* __restrict__ offsets, int* __restrict__ cursor,
                                const int* __restrict__ partials, int n)
{
    int i = blockIdx.x * blockDim.x + threadIdx.x;
    if (i < n) {
        int v = offsets[i] + partials[i >> 10];
        offsets[i] = v;
        cursor[i] = v;
    }
}

__global__ void build_perm_kernel(const int* __restrict__ seg, int* __restrict__ cursor,
                                  int* __restrict__ perm, int nnz)
{
    int i = blockIdx.x * blockDim.x + threadIdx.x;
    if (i < nnz) {
        int pos = atomicAdd(&cursor[seg[i]], 1);
        perm[pos] = i;
    }
}

__global__ void expsum_kernel(const float* __restrict__ score, const int* __restrict__ seg,
                              const float* __restrict__ segmax, float* __restrict__ expw,
                              float* __restrict__ segsum, int nnz)
{
    int i = blockIdx.x * blockDim.x + threadIdx.x;
    if (i < nnz) {
        const int sg = seg[i];
        float e = __expf(score[i] - segmax[sg]);
        expw[i] = e;
        atomicAdd(&segsum[sg], e);
    }
}

__global__ __launch_bounds__(256) void aggregate_kernel(
    const float* __restrict__ vmat,
    const int* __restrict__ rowidx,
    const int* __restrict__ offsets, const int* __restrict__ perm,
    const float* __restrict__ expw, const float* __restrict__ segsum,
    float* __restrict__ out, int nseg)
{
    __shared__ int   sh_r[128];
    __shared__ float sh_w[128];
    const int s = blockIdx.x;
    if (s >= nseg) return;
    const int d = threadIdx.x;
    const int beg = offsets[s];
    const int end = offsets[s + 1];
    float acc = 0.f;
    for (int cb = beg; cb < end; cb += 128) {
        const int m = min(128, end - cb);
        if (d < m) {
            const int nz = perm[cb + d];
            sh_w[d] = expw[nz];
            sh_r[d] = rowidx[nz];
        }
        __syncthreads();
        for (int j = 0; j < m; j++)
            acc += sh_w[j] * vmat[(size_t)sh_r[j] * 256 + d];
        __syncthreads();
    }
    const float denom = fmaxf(segsum[s], 1e-20f);
    out[(size_t)s * 256 + d] = fmaxf(acc / denom, 0.f);
}

// ---------------------------------------------------------------------------
// Launch
// ---------------------------------------------------------------------------
extern "C" void kernel_launch(void* const* d_in, const int* in_sizes, int n_in,
                              void* d_out, int out_size)
{
    const float* vfeat    = (const float*)d_in[0];
    const float* efeat    = (const float*)d_in[1];
    const int*   node_idx = (const int*)d_in[2];
    const int*   edge_idx = (const int*)d_in[3];
    const float* W_vtx = (const float*)d_in[4];  const float* b_vtx = (const float*)d_in[5];
    const float* W_qe  = (const float*)d_in[6];  const float* b_qe  = (const float*)d_in[7];
    const float* W_kv  = (const float*)d_in[8];  const float* b_kv  = (const float*)d_in[9];
    const float* W_vv  = (const float*)d_in[10]; const float* b_vv  = (const float*)d_in[11];
    const float* W_qv  = (const float*)d_in[12]; const float* b_qv  = (const float*)d_in[13];
    const float* W_ke  = (const float*)d_in[14]; const float* b_ke  = (const float*)d_in[15];
    const float* W_ve  = (const float*)d_in[16]; const float* b_ve  = (const float*)d_in[17];

    float* out_v = (float*)d_out;
    float* out_e = out_v + (size_t)N_NODES * VDIM;

    uint2 *vfeat_pk, *efeat_pk, *featv_pk, *feate_pk, *wpk;
    float *k1, *v1, *q2, *q1, *k2, *v2, *score, *expw, *segmax, *segsum;
    int *counts, *offsets, *cursor, *perm, *partials;
    cudaGetSymbolAddress((void**)&vfeat_pk, g_vfeat_pk);
    cudaGetSymbolAddress((void**)&efeat_pk, g_efeat_pk);
    cudaGetSymbolAddress((void**)&featv_pk, g_featv_pk);
    cudaGetSymbolAddress((void**)&feate_pk, g_feate_pk);
    cudaGetSymbolAddress((void**)&wpk, g_W_pk);
    cudaGetSymbolAddress((void**)&k1, g_k1);
    cudaGetSymbolAddress((void**)&v1, g_v1);
    cudaGetSymbolAddress((void**)&q2, g_q2);
    cudaGetSymbolAddress((void**)&q1, g_q1);
    cudaGetSymbolAddress((void**)&k2, g_k2);
    cudaGetSymbolAddress((void**)&v2, g_v2);
    cudaGetSymbolAddress((void**)&score, g_score);
    cudaGetSymbolAddress((void**)&expw, g_expw);
    cudaGetSymbolAddress((void**)&segmax, g_segmax);
    cudaGetSymbolAddress((void**)&segsum, g_segsum);
    cudaGetSymbolAddress((void**)&counts, g_counts);
    cudaGetSymbolAddress((void**)&offsets, g_offsets);
    cudaGetSymbolAddress((void**)&cursor, g_cursor);
    cudaGetSymbolAddress((void**)&perm, g_perm);
    cudaGetSymbolAddress((void**)&partials, g_partials);

    uint2* Wvtx_pk = wpk + 0 * 256 * KP;
    uint2* Wqe_pk  = wpk + 1 * 256 * KP;
    uint2* Wkv_pk  = wpk + 2 * 256 * KP;
    uint2* Wvv_pk  = wpk + 3 * 256 * KP;
    uint2* Wqv_pk  = wpk + 4 * 256 * KP;
    uint2* Wke_pk  = wpk + 5 * 256 * KP;
    uint2* Wve_pk  = wpk + 6 * 256 * KP;

    const int scoreBlocks = (NNZ * 32 + 255) / 256;
    const int nnzBlocks   = (NNZ + 255) / 256;

    // ---- one-time operand splits ----
    split_kernel<<<(N_NODES * KIN / 4 + 255) / 256, 256>>>(vfeat, vfeat_pk, N_NODES * KIN / 4);
    split_kernel<<<(N_EDGES * KIN / 4 + 255) / 256, 256>>>(efeat, efeat_pk, N_EDGES * KIN / 4);
    split_kernel<<<(VDIM * KIN / 4 + 255) / 256, 256>>>(W_vtx, Wvtx_pk, VDIM * KIN / 4);
    split_kernel<<<(QDIM * KIN / 4 + 255) / 256, 256>>>(W_qe,  Wqe_pk,  QDIM * KIN / 4);
    split_kernel<<<(QDIM * VDIM / 4 + 255) / 256, 256>>>(W_kv,  Wkv_pk,  QDIM * VDIM / 4);
    split_kernel<<<(EDIM * VDIM / 4 + 255) / 256, 256>>>(W_vv,  Wvv_pk,  EDIM * VDIM / 4);
    split_kernel<<<(QDIM * VDIM / 4 + 255) / 256, 256>>>(W_qv,  Wqv_pk,  QDIM * VDIM / 4);
    split_kernel<<<(QDIM * EDIM / 4 + 255) / 256, 256>>>(W_ke,  Wke_pk,  QDIM * EDIM / 4);
    split_kernel<<<(VDIM * EDIM / 4 + 255) / 256, 256>>>(W_ve,  Wve_pk,  VDIM * EDIM / 4);

    // ---- projections ----
    run_gemm_pk(vfeat_pk, Wvtx_pk, b_vtx, featv_pk, N_NODES, VDIM, KIN);
    run_gemm_f(featv_pk, Wkv_pk, b_kv, k1, N_NODES, QDIM, VDIM);
    run_gemm_f(featv_pk, Wvv_pk, b_vv, v1, N_NODES, EDIM, VDIM);
    run_gemm_f(featv_pk, Wqv_pk, b_qv, q2, N_NODES, QDIM, VDIM);
    run_gemm_f(efeat_pk, Wqe_pk, b_qe, q1, N_EDGES, QDIM, KIN);

    // ---- pass 1: nodes -> hyperedges ----
    {
        const int nseg = N_EDGES;
        const int nb = (nseg + 1023) / 1024;
        init_pass_kernel<<<(nseg + 255) / 256, 256>>>(segmax, segsum, counts, nseg);
        score_kernel<<<scoreBlocks, 256>>>(k1, q1, node_idx, edge_idx, edge_idx,
                                           score, segmax, counts, NNZ);
        scan_block_kernel<<<nb, 1024>>>(counts, offsets, partials, nseg);
        scan_partials_kernel<<<1, 64>>>(partials, offsets, nb, nseg);
        scan_add_kernel<<<(nseg + 255) / 256, 256>>>(offsets, cursor, partials, nseg);
        build_perm_kernel<<<nnzBlocks, 256>>>(edge_idx, cursor, perm, NNZ);
        expsum_kernel<<<nnzBlocks, 256>>>(score, edge_idx, segmax, expw, segsum, NNZ);
        aggregate_kernel<<<nseg, 256>>>(v1, node_idx, offsets, perm, expw, segsum,
                                        out_e, nseg);
    }

    // ---- packed copy of feat_e + edge-side projections ----
    split_kernel<<<(N_EDGES * EDIM / 4 + 255) / 256, 256>>>(out_e, feate_pk, N_EDGES * EDIM / 4);
    run_gemm_f(feate_pk, Wke_pk, b_ke, k2, N_EDGES, QDIM, EDIM);
    run_gemm_f(feate_pk, Wve_pk, b_ve, v2, N_EDGES, VDIM, EDIM);

    // ---- pass 2: hyperedges -> nodes ----
    {
        const int nseg = N_NODES;
        const int nb = (nseg + 1023) / 1024;
        init_pass_kernel<<<(nseg + 255) / 256, 256>>>(segmax, segsum, counts, nseg);
        score_kernel<<<scoreBlocks, 256>>>(k2, q2, edge_idx, node_idx, node_idx,
                                           score, segmax, counts, NNZ);
        scan_block_kernel<<<nb, 1024>>>(counts, offsets, partials, nseg);
        scan_partials_kernel<<<1, 64>>>(partials, offsets, nb, nseg);
        scan_add_kernel<<<(nseg + 255) / 256, 256>>>(offsets, cursor, partials, nseg);
        build_perm_kernel<<<nnzBlocks, 256>>>(node_idx, cursor, perm, NNZ);
        expsum_kernel<<<nnzBlocks, 256>>>(score, node_idx, segmax, expw, segsum, NNZ);
        aggregate_kernel<<<nseg, 256>>>(v2, edge_idx, offsets, perm, expw, segsum,
                                        out_v, nseg);
    }
}

// round 8
// speedup vs baseline: 1.0818x; 1.0769x over previous
#include <cuda_runtime.h>
#include <cuda_bf16.h>
#include <math.h>
#include <stdint.h>

// ---------------------------------------------------------------------------
// Problem constants
// ---------------------------------------------------------------------------
#define N_NODES 50000
#define N_EDGES 10000
#define NNZ     400000
#define QDIM    128
#define VDIM    256
#define EDIM    256
#define KIN     256
#define NEG_SLOPE 0.01f
#define SCORE_SCALE 0.08838834764831845f   // 1/sqrt(128)

// fused output 1: [N_NODES, 512] = k1(0..127) | v1(128..383) | q2(384..511)
#define F1W 512
// fused output 2: [N_EDGES, 384] = k2(0..127) | v2(128..383)
#define F2W 384

// ---------------------------------------------------------------------------
// Static scratch (no allocation allowed)
// ---------------------------------------------------------------------------
__device__ float g_feat_v[N_NODES * VDIM];
__device__ float g_fused1[N_NODES * F1W];
__device__ float g_fused2[N_EDGES * F2W];
__device__ float g_q1[N_EDGES * QDIM];
__device__ float g_Wcat1[F1W * VDIM];
__device__ float g_bcat1[F1W];
__device__ float g_Wcat2[F2W * EDIM];
__device__ float g_bcat2[F2W];
__device__ float g_score[NNZ];
__device__ float g_expw[NNZ];
__device__ float g_segmax[N_NODES];
__device__ float g_segsum[N_NODES];
__device__ int   g_counts[N_NODES];
__device__ int   g_offsets[N_NODES + 1];
__device__ int   g_cursor[N_NODES];
__device__ int   g_perm[NNZ];
__device__ int   g_partials[64];

// ---------------------------------------------------------------------------
// bf16-split tensor-core GEMM (R5 version — best measured).
// C[M,N] = A[M,K] @ W[N,K]^T + bias[N], computed as hh + hl + lh on
// mma.sync.m16n8k16.bf16 (fp32 accum).
// Block 128x64, BK=32, 256 threads = 8 warps (4m x 2n), warp tile 32x32.
// Requires N % 64 == 0, K % 32 == 0. M guarded.
// ---------------------------------------------------------------------------
#define BM 128
#define BN 64
#define BK 32
#define SS2 20   // row stride in uint2 units (conflict-free)

__device__ __forceinline__ void mma_bf16(float* c,
    uint32_t a0, uint32_t a1, uint32_t a2, uint32_t a3,
    uint32_t b0, uint32_t b1)
{
    asm volatile(
        "mma.sync.aligned.m16n8k16.row.col.f32.bf16.bf16.f32 "
        "{%0,%1,%2,%3}, {%4,%5,%6,%7}, {%8,%9}, {%0,%1,%2,%3};"
        : "+f"(c[0]), "+f"(c[1]), "+f"(c[2]), "+f"(c[3])
        : "r"(a0), "r"(a1), "r"(a2), "r"(a3), "r"(b0), "r"(b1));
}

__device__ __forceinline__ uint2 split2(float x0, float x1)
{
    __nv_bfloat16 h0 = __float2bfloat16_rn(x0);
    __nv_bfloat16 h1 = __float2bfloat16_rn(x1);
    __nv_bfloat16 l0 = __float2bfloat16_rn(x0 - __bfloat162float(h0));
    __nv_bfloat16 l1 = __float2bfloat16_rn(x1 - __bfloat162float(h1));
    uint2 r;
    r.x = (uint32_t)__bfloat16_as_ushort(h0) | ((uint32_t)__bfloat16_as_ushort(h1) << 16);
    r.y = (uint32_t)__bfloat16_as_ushort(l0) | ((uint32_t)__bfloat16_as_ushort(l1) << 16);
    return r;
}

__global__ __launch_bounds__(256, 2) void gemm_bf16_kernel(
    const float* __restrict__ A, const float* __restrict__ W,
    const float* __restrict__ bias, float* __restrict__ C,
    int M, int N, int K)
{
    __shared__ uint2 As2[BM][SS2];
    __shared__ uint2 Bs2[BN][SS2];

    const int t    = threadIdx.x;
    const int lane = t & 31;
    const int wid  = t >> 5;
    const int wm   = wid & 3;
    const int wn   = wid >> 2;
    const int g    = lane >> 2;
    const int t4   = lane & 3;

    const int block_m = blockIdx.y * BM;
    const int block_n = blockIdx.x * BN;

    const int arow_i = t >> 1;
    const int aseg   = (t & 1) * 16;
    const int brow_i = t >> 2;
    const int bseg   = (t & 3) * 8;
    const int gma = block_m + arow_i;
    const float* aptr = A + (size_t)(gma < M ? gma : (M - 1)) * K + aseg;
    const float* bptr = W + (size_t)(block_n + brow_i) * K + bseg;

    float acc[2][4][4];
#pragma unroll
    for (int i = 0; i < 2; i++)
#pragma unroll
        for (int j = 0; j < 4; j++)
#pragma unroll
            for (int l = 0; l < 4; l++) acc[i][j][l] = 0.f;

    float4 pa[4], pb[2];
#pragma unroll
    for (int u = 0; u < 4; u++) pa[u] = *(const float4*)(aptr + u * 4);
#pragma unroll
    for (int u = 0; u < 2; u++) pb[u] = *(const float4*)(bptr + u * 4);

    const int NC = K / BK;
    for (int c = 0; c < NC; c++) {
#pragma unroll
        for (int u = 0; u < 4; u++) {
            uint2 p0 = split2(pa[u].x, pa[u].y);
            uint2 p1 = split2(pa[u].z, pa[u].w);
            asm volatile("st.shared.v4.b32 [%0], {%1,%2,%3,%4};" ::
                "l"(__cvta_generic_to_shared(&As2[arow_i][aseg / 2 + u * 2])),
                "r"(p0.x), "r"(p0.y), "r"(p1.x), "r"(p1.y) : "memory");
        }
#pragma unroll
        for (int u = 0; u < 2; u++) {
            uint2 p0 = split2(pb[u].x, pb[u].y);
            uint2 p1 = split2(pb[u].z, pb[u].w);
            asm volatile("st.shared.v4.b32 [%0], {%1,%2,%3,%4};" ::
                "l"(__cvta_generic_to_shared(&Bs2[brow_i][bseg / 2 + u * 2])),
                "r"(p0.x), "r"(p0.y), "r"(p1.x), "r"(p1.y) : "memory");
        }
        __syncthreads();

        if (c + 1 < NC) {
            const int k1o = (c + 1) * BK;
#pragma unroll
            for (int u = 0; u < 4; u++) pa[u] = *(const float4*)(aptr + k1o + u * 4);
#pragma unroll
            for (int u = 0; u < 2; u++) pb[u] = *(const float4*)(bptr + k1o + u * 4);
        }

#pragma unroll
        for (int kk = 0; kk < 2; kk++) {
            const int kc0 = kk * 8 + t4;
            const int kc1 = kc0 + 4;
            uint32_t ahi[2][4], alo[2][4];
#pragma unroll
            for (int mt = 0; mt < 2; mt++) {
                const int r0 = wm * 32 + mt * 16 + g;
                uint2 v0 = As2[r0][kc0];
                uint2 v1 = As2[r0 + 8][kc0];
                uint2 v2 = As2[r0][kc1];
                uint2 v3 = As2[r0 + 8][kc1];
                ahi[mt][0] = v0.x; alo[mt][0] = v0.y;
                ahi[mt][1] = v1.x; alo[mt][1] = v1.y;
                ahi[mt][2] = v2.x; alo[mt][2] = v2.y;
                ahi[mt][3] = v3.x; alo[mt][3] = v3.y;
            }
            uint32_t bhi[4][2], blo[4][2];
#pragma unroll
            for (int nt = 0; nt < 4; nt++) {
                const int n0 = wn * 32 + nt * 8 + g;
                uint2 u0 = Bs2[n0][kc0];
                uint2 u1 = Bs2[n0][kc1];
                bhi[nt][0] = u0.x; blo[nt][0] = u0.y;
                bhi[nt][1] = u1.x; blo[nt][1] = u1.y;
            }
#pragma unroll
            for (int mt = 0; mt < 2; mt++)
#pragma unroll
                for (int nt = 0; nt < 4; nt++)
                    mma_bf16(acc[mt][nt], ahi[mt][0], ahi[mt][1], ahi[mt][2], ahi[mt][3],
                             bhi[nt][0], bhi[nt][1]);
#pragma unroll
            for (int mt = 0; mt < 2; mt++)
#pragma unroll
                for (int nt = 0; nt < 4; nt++)
                    mma_bf16(acc[mt][nt], ahi[mt][0], ahi[mt][1], ahi[mt][2], ahi[mt][3],
                             blo[nt][0], blo[nt][1]);
#pragma unroll
            for (int mt = 0; mt < 2; mt++)
#pragma unroll
                for (int nt = 0; nt < 4; nt++)
                    mma_bf16(acc[mt][nt], alo[mt][0], alo[mt][1], alo[mt][2], alo[mt][3],
                             bhi[nt][0], bhi[nt][1]);
        }
        __syncthreads();
    }

#pragma unroll
    for (int mt = 0; mt < 2; mt++) {
#pragma unroll
        for (int nt = 0; nt < 4; nt++) {
            const int m0 = block_m + wm * 32 + mt * 16 + g;
            const int n0 = block_n + wn * 32 + nt * 8 + t4 * 2;
            const float bv0 = bias[n0], bv1 = bias[n0 + 1];
            if (m0 < M) {
                float2 o = make_float2(acc[mt][nt][0] + bv0, acc[mt][nt][1] + bv1);
                *(float2*)&C[(size_t)m0 * N + n0] = o;
            }
            if (m0 + 8 < M) {
                float2 o = make_float2(acc[mt][nt][2] + bv0, acc[mt][nt][3] + bv1);
                *(float2*)&C[(size_t)(m0 + 8) * N + n0] = o;
            }
        }
    }
}

static void run_gemm(const float* A, const float* W, const float* b, float* C,
                     int M, int N, int K)
{
    dim3 grid(N / BN, (M + BM - 1) / BM);
    gemm_bf16_kernel<<<grid, 256>>>(A, W, b, C, M, N, K);
}

// ---------------------------------------------------------------------------
// Softmax / segment machinery
// ---------------------------------------------------------------------------
__device__ __forceinline__ void atomicMaxFloat(float* addr, float val)
{
    if (val >= 0.f)
        atomicMax((int*)addr, __float_as_int(val));
    else
        atomicMin((unsigned int*)addr, __float_as_uint(val));
}

__global__ void init_pass_kernel(float* segmax, float* segsum, int* counts, int nseg)
{
    int i = blockIdx.x * blockDim.x + threadIdx.x;
    if (i < nseg) {
        segmax[i] = -INFINITY;
        segsum[i] = 0.f;
        counts[i] = 0;
    }
}

// scores with row strides (fused buffers)
__global__ __launch_bounds__(256) void score_kernel(
    const float* __restrict__ kmat, int kstride,
    const float* __restrict__ qmat, int qstride,
    const int* __restrict__ kidx, const int* __restrict__ qidx,
    const int* __restrict__ seg,
    float* __restrict__ score, float* __restrict__ segmax, int* __restrict__ counts,
    int nnz)
{
    const int w = (blockIdx.x * blockDim.x + threadIdx.x) >> 5;
    const int lane = threadIdx.x & 31;
    if (w >= nnz) return;
    const int ki = kidx[w];
    const int qi = qidx[w];
    float4 a = *(const float4*)&kmat[(size_t)ki * kstride + lane * 4];
    float4 b = *(const float4*)&qmat[(size_t)qi * qstride + lane * 4];
    float d = a.x * b.x + a.y * b.y + a.z * b.z + a.w * b.w;
#pragma unroll
    for (int o = 16; o > 0; o >>= 1) d += __shfl_xor_sync(0xffffffffu, d, o);
    if (lane == 0) {
        float s = (d >= 0.f ? d : NEG_SLOPE * d) * SCORE_SCALE;
        score[w] = s;
        const int sg = seg[w];
        atomicMaxFloat(&segmax[sg], s);
        atomicAdd(&counts[sg], 1);
    }
}

__global__ __launch_bounds__(1024) void scan_block_kernel(
    const int* __restrict__ counts, int* __restrict__ offsets,
    int* __restrict__ partials, int n)
{
    __shared__ int sh[1024];
    const int t = threadIdx.x;
    const int i = blockIdx.x * 1024 + t;
    const int x = (i < n) ? counts[i] : 0;
    sh[t] = x;
    __syncthreads();
    for (int off = 1; off < 1024; off <<= 1) {
        int v = (t >= off) ? sh[t - off] : 0;
        __syncthreads();
        sh[t] += v;
        __syncthreads();
    }
    if (i < n) offsets[i] = sh[t] - x;
    if (t == 1023) partials[blockIdx.x] = sh[1023];
}

__global__ void scan_partials_kernel(int* partials, int* offsets, int nb, int n)
{
    __shared__ int sh[64];
    const int t = threadIdx.x;
    const int x = (t < nb) ? partials[t] : 0;
    sh[t] = x;
    __syncthreads();
    for (int off = 1; off < 64; off <<= 1) {
        int v = (t >= off) ? sh[t - off] : 0;
        __syncthreads();
        sh[t] += v;
        __syncthreads();
    }
    if (t < nb) partials[t] = sh[t] - x;
    if (t == 63) offsets[n] = sh[63];
}

__global__ void scan_add_kernel(int* __restrict__ offsets, int* __restrict__ cursor,
                                const int* __restrict__ partials, int n)
{
    int i = blockIdx.x * blockDim.x + threadIdx.x;
    if (i < n) {
        int v = offsets[i] + partials[i >> 10];
        offsets[i] = v;
        cursor[i] = v;
    }
}

// fused: exp-weight + segment-sum + permutation build (one pass over nnz)
__global__ void expsum_perm_kernel(
    const float* __restrict__ score, const int* __restrict__ seg,
    const float* __restrict__ segmax, float* __restrict__ expw,
    float* __restrict__ segsum, int* __restrict__ cursor, int* __restrict__ perm,
    int nnz)
{
    int i = blockIdx.x * blockDim.x + threadIdx.x;
    if (i < nnz) {
        const int sg = seg[i];
        int pos = atomicAdd(&cursor[sg], 1);
        perm[pos] = i;
        float e = __expf(score[i] - segmax[sg]);
        expw[i] = e;
        atomicAdd(&segsum[sg], e);
    }
}

__global__ __launch_bounds__(256) void aggregate_kernel(
    const float* __restrict__ vmat, int vstride,
    const int* __restrict__ rowidx,
    const int* __restrict__ offsets, const int* __restrict__ perm,
    const float* __restrict__ expw, const float* __restrict__ segsum,
    float* __restrict__ out, int nseg)
{
    __shared__ int   sh_r[128];
    __shared__ float sh_w[128];
    const int s = blockIdx.x;
    if (s >= nseg) return;
    const int d = threadIdx.x;
    const int beg = offsets[s];
    const int end = offsets[s + 1];
    float acc = 0.f;
    for (int cb = beg; cb < end; cb += 128) {
        const int m = min(128, end - cb);
        if (d < m) {
            const int nz = perm[cb + d];
            sh_w[d] = expw[nz];
            sh_r[d] = rowidx[nz];
        }
        __syncthreads();
        for (int j = 0; j < m; j++)
            acc += sh_w[j] * vmat[(size_t)sh_r[j] * vstride + d];
        __syncthreads();
    }
    const float denom = fmaxf(segsum[s], 1e-20f);
    out[(size_t)s * 256 + d] = fmaxf(acc / denom, 0.f);
}

// ---------------------------------------------------------------------------
// Launch
// ---------------------------------------------------------------------------
extern "C" void kernel_launch(void* const* d_in, const int* in_sizes, int n_in,
                              void* d_out, int out_size)
{
    const float* vfeat    = (const float*)d_in[0];
    const float* efeat    = (const float*)d_in[1];
    const int*   node_idx = (const int*)d_in[2];
    const int*   edge_idx = (const int*)d_in[3];
    const float* W_vtx = (const float*)d_in[4];  const float* b_vtx = (const float*)d_in[5];
    const float* W_qe  = (const float*)d_in[6];  const float* b_qe  = (const float*)d_in[7];
    const float* W_kv  = (const float*)d_in[8];  const float* b_kv  = (const float*)d_in[9];
    const float* W_vv  = (const float*)d_in[10]; const float* b_vv  = (const float*)d_in[11];
    const float* W_qv  = (const float*)d_in[12]; const float* b_qv  = (const float*)d_in[13];
    const float* W_ke  = (const float*)d_in[14]; const float* b_ke  = (const float*)d_in[15];
    const float* W_ve  = (const float*)d_in[16]; const float* b_ve  = (const float*)d_in[17];

    float* out_v = (float*)d_out;
    float* out_e = out_v + (size_t)N_NODES * VDIM;

    float *feat_v, *fused1, *fused2, *q1, *Wcat1, *bcat1, *Wcat2, *bcat2;
    float *score, *expw, *segmax, *segsum;
    int *counts, *offsets, *cursor, *perm, *partials;
    cudaGetSymbolAddress((void**)&feat_v, g_feat_v);
    cudaGetSymbolAddress((void**)&fused1, g_fused1);
    cudaGetSymbolAddress((void**)&fused2, g_fused2);
    cudaGetSymbolAddress((void**)&q1, g_q1);
    cudaGetSymbolAddress((void**)&Wcat1, g_Wcat1);
    cudaGetSymbolAddress((void**)&bcat1, g_bcat1);
    cudaGetSymbolAddress((void**)&Wcat2, g_Wcat2);
    cudaGetSymbolAddress((void**)&bcat2, g_bcat2);
    cudaGetSymbolAddress((void**)&score, g_score);
    cudaGetSymbolAddress((void**)&expw, g_expw);
    cudaGetSymbolAddress((void**)&segmax, g_segmax);
    cudaGetSymbolAddress((void**)&segsum, g_segsum);
    cudaGetSymbolAddress((void**)&counts, g_counts);
    cudaGetSymbolAddress((void**)&offsets, g_offsets);
    cudaGetSymbolAddress((void**)&cursor, g_cursor);
    cudaGetSymbolAddress((void**)&perm, g_perm);
    cudaGetSymbolAddress((void**)&partials, g_partials);

    const int scoreBlocks = (NNZ * 32 + 255) / 256;
    const int nnzBlocks   = (NNZ + 255) / 256;

    // ---- concat weights/biases for fused GEMMs (D2D copies, capture-legal) ----
    // fused1: rows [0,128)=W_kv, [128,384)=W_vv, [384,512)=W_qv  (all K=256)
    cudaMemcpyAsync(Wcat1,             W_kv, (size_t)QDIM * VDIM * 4, cudaMemcpyDeviceToDevice);
    cudaMemcpyAsync(Wcat1 + 128 * 256, W_vv, (size_t)EDIM * VDIM * 4, cudaMemcpyDeviceToDevice);
    cudaMemcpyAsync(Wcat1 + 384 * 256, W_qv, (size_t)QDIM * VDIM * 4, cudaMemcpyDeviceToDevice);
    cudaMemcpyAsync(bcat1,       b_kv, QDIM * 4, cudaMemcpyDeviceToDevice);
    cudaMemcpyAsync(bcat1 + 128, b_vv, EDIM * 4, cudaMemcpyDeviceToDevice);
    cudaMemcpyAsync(bcat1 + 384, b_qv, QDIM * 4, cudaMemcpyDeviceToDevice);
    // fused2: rows [0,128)=W_ke, [128,384)=W_ve  (all K=256)
    cudaMemcpyAsync(Wcat2,             W_ke, (size_t)QDIM * EDIM * 4, cudaMemcpyDeviceToDevice);
    cudaMemcpyAsync(Wcat2 + 128 * 256, W_ve, (size_t)VDIM * EDIM * 4, cudaMemcpyDeviceToDevice);
    cudaMemcpyAsync(bcat2,       b_ke, QDIM * 4, cudaMemcpyDeviceToDevice);
    cudaMemcpyAsync(bcat2 + 128, b_ve, VDIM * 4, cudaMemcpyDeviceToDevice);

    // ---- projections ----
    run_gemm(vfeat,  W_vtx, b_vtx, feat_v, N_NODES, VDIM, KIN);       // feat_v
    run_gemm(feat_v, Wcat1, bcat1, fused1, N_NODES, F1W,  VDIM);      // k1|v1|q2
    run_gemm(efeat,  W_qe,  b_qe,  q1,     N_EDGES, QDIM, KIN);       // q1

    // ---- pass 1: nodes -> hyperedges (seg = edge_idx, nseg = N_EDGES) ----
    {
        const int nseg = N_EDGES;
        const int nb = (nseg + 1023) / 1024;
        init_pass_kernel<<<(nseg + 255) / 256, 256>>>(segmax, segsum, counts, nseg);
        score_kernel<<<scoreBlocks, 256>>>(fused1, F1W, q1, QDIM,
                                           node_idx, edge_idx, edge_idx,
                                           score, segmax, counts, NNZ);
        scan_block_kernel<<<nb, 1024>>>(counts, offsets, partials, nseg);
        scan_partials_kernel<<<1, 64>>>(partials, offsets, nb, nseg);
        scan_add_kernel<<<(nseg + 255) / 256, 256>>>(offsets, cursor, partials, nseg);
        expsum_perm_kernel<<<nnzBlocks, 256>>>(score, edge_idx, segmax, expw, segsum,
                                               cursor, perm, NNZ);
        aggregate_kernel<<<nseg, 256>>>(fused1 + 128, F1W, node_idx, offsets, perm,
                                        expw, segsum, out_e, nseg);   // feat_e
    }

    // ---- edge-side fused projection ----
    run_gemm(out_e, Wcat2, bcat2, fused2, N_EDGES, F2W, EDIM);        // k2|v2

    // ---- pass 2: hyperedges -> nodes (seg = node_idx, nseg = N_NODES) ----
    {
        const int nseg = N_NODES;
        const int nb = (nseg + 1023) / 1024;
        init_pass_kernel<<<(nseg + 255) / 256, 256>>>(segmax, segsum, counts, nseg);
        score_kernel<<<scoreBlocks, 256>>>(fused2, F2W, fused1 + 384, F1W,
                                           edge_idx, node_idx, node_idx,
                                           score, segmax, counts, NNZ);
        scan_block_kernel<<<nb, 1024>>>(counts, offsets, partials, nseg);
        scan_partials_kernel<<<1, 64>>>(partials, offsets, nb, nseg);
        scan_add_kernel<<<(nseg + 255) / 256, 256>>>(offsets, cursor, partials, nseg);
        expsum_perm_kernel<<<nnzBlocks, 256>>>(score, node_idx, segmax, expw, segsum,
                                               cursor, perm, NNZ);
        aggregate_kernel<<<nseg, 256>>>(fused2 + 128, F2W, edge_idx, offsets, perm,
                                        expw, segsum, out_v, nseg);   // feat_v_out
    }
}

// round 9
// speedup vs baseline: 1.1550x; 1.0677x over previous
#include <cuda_runtime.h>
#include <cuda_bf16.h>
#include <math.h>
#include <stdint.h>

// ---------------------------------------------------------------------------
// Problem constants
// ---------------------------------------------------------------------------
#define N_NODES 50000
#define N_EDGES 10000
#define NNZ     400000
#define QDIM    128
#define VDIM    256
#define EDIM    256
#define KIN     256
#define NEG_SLOPE 0.01f
#define SCORE_SCALE 0.08838834764831845f   // 1/sqrt(128)

// fused output 1: [N_NODES, 512] = k1(0..127) | v1(128..383) | q2(384..511)
#define F1W 512
// fused output 2: [N_EDGES, 384] = k2(0..127) | v2(128..383)
#define F2W 384

// ---------------------------------------------------------------------------
// Static scratch (no allocation allowed)
// ---------------------------------------------------------------------------
__device__ float g_fused1[N_NODES * F1W];
__device__ float g_fused2[N_EDGES * F2W];
__device__ float g_q1[N_EDGES * QDIM];
__device__ float g_Wcomb[F1W * KIN];
__device__ float g_bcomb[F1W];
__device__ float g_Wcat2[F2W * EDIM];
__device__ float g_bcat2[F2W];
__device__ float g_score[NNZ];
__device__ float g_expw[NNZ];
__device__ float g_segmax[N_NODES];
__device__ float g_segsum[N_NODES];
__device__ int   g_counts[N_NODES];
__device__ int   g_offsets[N_NODES + 1];
__device__ int   g_cursor[N_NODES];
__device__ int   g_perm[NNZ];
__device__ int   g_partials[64];

// ---------------------------------------------------------------------------
// Weight combination: Wcomb[o,i] = sum_v Wcat1[o,v] * Wvtx[v,i]
// where Wcat1 rows: [0,128)=W_kv, [128,384)=W_vv, [384,512)=W_qv.
// fp32, exact up to fp32 rounding. 64 blocks x 8 rows, 256 threads.
// ---------------------------------------------------------------------------
__global__ __launch_bounds__(256) void combine_w_kernel(
    const float* __restrict__ Wkv, const float* __restrict__ Wvv,
    const float* __restrict__ Wqv, const float* __restrict__ Wvtx,
    float* __restrict__ Wcomb)
{
    __shared__ float a[8][256];
    const int ob = blockIdx.x * 8;
    const int i = threadIdx.x;
#pragma unroll
    for (int r = 0; r < 8; r++) {
        const int o = ob + r;
        const float* src = (o < 128) ? Wkv + (size_t)o * 256
                         : (o < 384) ? Wvv + (size_t)(o - 128) * 256
                                     : Wqv + (size_t)(o - 384) * 256;
        a[r][i] = src[i];
    }
    __syncthreads();
    float s[8];
#pragma unroll
    for (int r = 0; r < 8; r++) s[r] = 0.f;
    for (int v = 0; v < 256; v++) {
        const float w = Wvtx[(size_t)v * 256 + i];
#pragma unroll
        for (int r = 0; r < 8; r++) s[r] += a[r][v] * w;
    }
#pragma unroll
    for (int r = 0; r < 8; r++) Wcomb[(size_t)(ob + r) * 256 + i] = s[r];
}

__global__ void combine_b_kernel(
    const float* __restrict__ Wkv, const float* __restrict__ Wvv,
    const float* __restrict__ Wqv,
    const float* __restrict__ bkv, const float* __restrict__ bvv,
    const float* __restrict__ bqv, const float* __restrict__ bvtx,
    float* __restrict__ bcomb)
{
    const int o = blockIdx.x * blockDim.x + threadIdx.x;
    if (o >= F1W) return;
    const float* wsrc;
    float b;
    if (o < 128)      { wsrc = Wkv + (size_t)o * 256;         b = bkv[o]; }
    else if (o < 384) { wsrc = Wvv + (size_t)(o - 128) * 256; b = bvv[o - 128]; }
    else              { wsrc = Wqv + (size_t)(o - 384) * 256; b = bqv[o - 384]; }
    float s = b;
    for (int v = 0; v < 256; v++) s += wsrc[v] * bvtx[v];
    bcomb[o] = s;
}

// ---------------------------------------------------------------------------
// bf16-split tensor-core GEMM (best measured variant).
// C[M,N] = A[M,K] @ W[N,K]^T + bias[N], computed as hh + hl + lh on
// mma.sync.m16n8k16.bf16 (fp32 accum).
// Block 128x64, BK=32, 256 threads = 8 warps (4m x 2n), warp tile 32x32.
// ---------------------------------------------------------------------------
#define BM 128
#define BN 64
#define BK 32
#define SS2 20

__device__ __forceinline__ void mma_bf16(float* c,
    uint32_t a0, uint32_t a1, uint32_t a2, uint32_t a3,
    uint32_t b0, uint32_t b1)
{
    asm volatile(
        "mma.sync.aligned.m16n8k16.row.col.f32.bf16.bf16.f32 "
        "{%0,%1,%2,%3}, {%4,%5,%6,%7}, {%8,%9}, {%0,%1,%2,%3};"
        : "+f"(c[0]), "+f"(c[1]), "+f"(c[2]), "+f"(c[3])
        : "r"(a0), "r"(a1), "r"(a2), "r"(a3), "r"(b0), "r"(b1));
}

__device__ __forceinline__ uint2 split2(float x0, float x1)
{
    __nv_bfloat16 h0 = __float2bfloat16_rn(x0);
    __nv_bfloat16 h1 = __float2bfloat16_rn(x1);
    __nv_bfloat16 l0 = __float2bfloat16_rn(x0 - __bfloat162float(h0));
    __nv_bfloat16 l1 = __float2bfloat16_rn(x1 - __bfloat162float(h1));
    uint2 r;
    r.x = (uint32_t)__bfloat16_as_ushort(h0) | ((uint32_t)__bfloat16_as_ushort(h1) << 16);
    r.y = (uint32_t)__bfloat16_as_ushort(l0) | ((uint32_t)__bfloat16_as_ushort(l1) << 16);
    return r;
}

__global__ __launch_bounds__(256, 2) void gemm_bf16_kernel(
    const float* __restrict__ A, const float* __restrict__ W,
    const float* __restrict__ bias, float* __restrict__ C,
    int M, int N, int K)
{
    __shared__ uint2 As2[BM][SS2];
    __shared__ uint2 Bs2[BN][SS2];

    const int t    = threadIdx.x;
    const int lane = t & 31;
    const int wid  = t >> 5;
    const int wm   = wid & 3;
    const int wn   = wid >> 2;
    const int g    = lane >> 2;
    const int t4   = lane & 3;

    const int block_m = blockIdx.y * BM;
    const int block_n = blockIdx.x * BN;

    const int arow_i = t >> 1;
    const int aseg   = (t & 1) * 16;
    const int brow_i = t >> 2;
    const int bseg   = (t & 3) * 8;
    const int gma = block_m + arow_i;
    const float* aptr = A + (size_t)(gma < M ? gma : (M - 1)) * K + aseg;
    const float* bptr = W + (size_t)(block_n + brow_i) * K + bseg;

    float acc[2][4][4];
#pragma unroll
    for (int i = 0; i < 2; i++)
#pragma unroll
        for (int j = 0; j < 4; j++)
#pragma unroll
            for (int l = 0; l < 4; l++) acc[i][j][l] = 0.f;

    float4 pa[4], pb[2];
#pragma unroll
    for (int u = 0; u < 4; u++) pa[u] = *(const float4*)(aptr + u * 4);
#pragma unroll
    for (int u = 0; u < 2; u++) pb[u] = *(const float4*)(bptr + u * 4);

    const int NC = K / BK;
    for (int c = 0; c < NC; c++) {
#pragma unroll
        for (int u = 0; u < 4; u++) {
            uint2 p0 = split2(pa[u].x, pa[u].y);
            uint2 p1 = split2(pa[u].z, pa[u].w);
            asm volatile("st.shared.v4.b32 [%0], {%1,%2,%3,%4};" ::
                "l"(__cvta_generic_to_shared(&As2[arow_i][aseg / 2 + u * 2])),
                "r"(p0.x), "r"(p0.y), "r"(p1.x), "r"(p1.y) : "memory");
        }
#pragma unroll
        for (int u = 0; u < 2; u++) {
            uint2 p0 = split2(pb[u].x, pb[u].y);
            uint2 p1 = split2(pb[u].z, pb[u].w);
            asm volatile("st.shared.v4.b32 [%0], {%1,%2,%3,%4};" ::
                "l"(__cvta_generic_to_shared(&Bs2[brow_i][bseg / 2 + u * 2])),
                "r"(p0.x), "r"(p0.y), "r"(p1.x), "r"(p1.y) : "memory");
        }
        __syncthreads();

        if (c + 1 < NC) {
            const int k1o = (c + 1) * BK;
#pragma unroll
            for (int u = 0; u < 4; u++) pa[u] = *(const float4*)(aptr + k1o + u * 4);
#pragma unroll
            for (int u = 0; u < 2; u++) pb[u] = *(const float4*)(bptr + k1o + u * 4);
        }

#pragma unroll
        for (int kk = 0; kk < 2; kk++) {
            const int kc0 = kk * 8 + t4;
            const int kc1 = kc0 + 4;
            uint32_t ahi[2][4], alo[2][4];
#pragma unroll
            for (int mt = 0; mt < 2; mt++) {
                const int r0 = wm * 32 + mt * 16 + g;
                uint2 v0 = As2[r0][kc0];
                uint2 v1 = As2[r0 + 8][kc0];
                uint2 v2 = As2[r0][kc1];
                uint2 v3 = As2[r0 + 8][kc1];
                ahi[mt][0] = v0.x; alo[mt][0] = v0.y;
                ahi[mt][1] = v1.x; alo[mt][1] = v1.y;
                ahi[mt][2] = v2.x; alo[mt][2] = v2.y;
                ahi[mt][3] = v3.x; alo[mt][3] = v3.y;
            }
            uint32_t bhi[4][2], blo[4][2];
#pragma unroll
            for (int nt = 0; nt < 4; nt++) {
                const int n0 = wn * 32 + nt * 8 + g;
                uint2 u0 = Bs2[n0][kc0];
                uint2 u1 = Bs2[n0][kc1];
                bhi[nt][0] = u0.x; blo[nt][0] = u0.y;
                bhi[nt][1] = u1.x; blo[nt][1] = u1.y;
            }
#pragma unroll
            for (int mt = 0; mt < 2; mt++)
#pragma unroll
                for (int nt = 0; nt < 4; nt++)
                    mma_bf16(acc[mt][nt], ahi[mt][0], ahi[mt][1], ahi[mt][2], ahi[mt][3],
                             bhi[nt][0], bhi[nt][1]);
#pragma unroll
            for (int mt = 0; mt < 2; mt++)
#pragma unroll
                for (int nt = 0; nt < 4; nt++)
                    mma_bf16(acc[mt][nt], ahi[mt][0], ahi[mt][1], ahi[mt][2], ahi[mt][3],
                             blo[nt][0], blo[nt][1]);
#pragma unroll
            for (int mt = 0; mt < 2; mt++)
#pragma unroll
                for (int nt = 0; nt < 4; nt++)
                    mma_bf16(acc[mt][nt], alo[mt][0], alo[mt][1], alo[mt][2], alo[mt][3],
                             bhi[nt][0], bhi[nt][1]);
        }
        __syncthreads();
    }

#pragma unroll
    for (int mt = 0; mt < 2; mt++) {
#pragma unroll
        for (int nt = 0; nt < 4; nt++) {
            const int m0 = block_m + wm * 32 + mt * 16 + g;
            const int n0 = block_n + wn * 32 + nt * 8 + t4 * 2;
            const float bv0 = bias[n0], bv1 = bias[n0 + 1];
            if (m0 < M) {
                float2 o = make_float2(acc[mt][nt][0] + bv0, acc[mt][nt][1] + bv1);
                *(float2*)&C[(size_t)m0 * N + n0] = o;
            }
            if (m0 + 8 < M) {
                float2 o = make_float2(acc[mt][nt][2] + bv0, acc[mt][nt][3] + bv1);
                *(float2*)&C[(size_t)(m0 + 8) * N + n0] = o;
            }
        }
    }
}

static void run_gemm(const float* A, const float* W, const float* b, float* C,
                     int M, int N, int K)
{
    dim3 grid(N / BN, (M + BM - 1) / BM);
    gemm_bf16_kernel<<<grid, 256>>>(A, W, b, C, M, N, K);
}

// ---------------------------------------------------------------------------
// Softmax / segment machinery
// ---------------------------------------------------------------------------
__device__ __forceinline__ void atomicMaxFloat(float* addr, float val)
{
    if (val >= 0.f)
        atomicMax((int*)addr, __float_as_int(val));
    else
        atomicMin((unsigned int*)addr, __float_as_uint(val));
}

__global__ void init_pass_kernel(float* segmax, float* segsum, int* counts, int nseg)
{
    int i = blockIdx.x * blockDim.x + threadIdx.x;
    if (i < nseg) {
        segmax[i] = -INFINITY;
        segsum[i] = 0.f;
        counts[i] = 0;
    }
}

__global__ __launch_bounds__(256) void score_kernel(
    const float* __restrict__ kmat, int kstride,
    const float* __restrict__ qmat, int qstride,
    const int* __restrict__ kidx, const int* __restrict__ qidx,
    const int* __restrict__ seg,
    float* __restrict__ score, float* __restrict__ segmax, int* __restrict__ counts,
    int nnz)
{
    const int w = (blockIdx.x * blockDim.x + threadIdx.x) >> 5;
    const int lane = threadIdx.x & 31;
    if (w >= nnz) return;
    const int ki = kidx[w];
    const int qi = qidx[w];
    float4 a = *(const float4*)&kmat[(size_t)ki * kstride + lane * 4];
    float4 b = *(const float4*)&qmat[(size_t)qi * qstride + lane * 4];
    float d = a.x * b.x + a.y * b.y + a.z * b.z + a.w * b.w;
#pragma unroll
    for (int o = 16; o > 0; o >>= 1) d += __shfl_xor_sync(0xffffffffu, d, o);
    if (lane == 0) {
        float s = (d >= 0.f ? d : NEG_SLOPE * d) * SCORE_SCALE;
        score[w] = s;
        const int sg = seg[w];
        atomicMaxFloat(&segmax[sg], s);
        atomicAdd(&counts[sg], 1);
    }
}

__global__ __launch_bounds__(1024) void scan_block_kernel(
    const int* __restrict__ counts, int* __restrict__ offsets,
    int* __restrict__ partials, int n)
{
    __shared__ int sh[1024];
    const int t = threadIdx.x;
    const int i = blockIdx.x * 1024 + t;
    const int x = (i < n) ? counts[i] : 0;
    sh[t] = x;
    __syncthreads();
    for (int off = 1; off < 1024; off <<= 1) {
        int v = (t >= off) ? sh[t - off] : 0;
        __syncthreads();
        sh[t] += v;
        __syncthreads();
    }
    if (i < n) offsets[i] = sh[t] - x;
    if (t == 1023) partials[blockIdx.x] = sh[1023];
}

__global__ void scan_partials_kernel(int* partials, int* offsets, int nb, int n)
{
    __shared__ int sh[64];
    const int t = threadIdx.x;
    const int x = (t < nb) ? partials[t] : 0;
    sh[t] = x;
    __syncthreads();
    for (int off = 1; off < 64; off <<= 1) {
        int v = (t >= off) ? sh[t - off] : 0;
        __syncthreads();
        sh[t] += v;
        __syncthreads();
    }
    if (t < nb) partials[t] = sh[t] - x;
    if (t == 63) offsets[n] = sh[63];
}

__global__ void scan_add_kernel(int* __restrict__ offsets, int* __restrict__ cursor,
                                const int* __restrict__ partials, int n)
{
    int i = blockIdx.x * blockDim.x + threadIdx.x;
    if (i < n) {
        int v = offsets[i] + partials[i >> 10];
        offsets[i] = v;
        cursor[i] = v;
    }
}

__global__ void expsum_perm_kernel(
    const float* __restrict__ score, const int* __restrict__ seg,
    const float* __restrict__ segmax, float* __restrict__ expw,
    float* __restrict__ segsum, int* __restrict__ cursor, int* __restrict__ perm,
    int nnz)
{
    int i = blockIdx.x * blockDim.x + threadIdx.x;
    if (i < nnz) {
        const int sg = seg[i];
        int pos = atomicAdd(&cursor[sg], 1);
        perm[pos] = i;
        float e = __expf(score[i] - segmax[sg]);
        expw[i] = e;
        atomicAdd(&segsum[sg], e);
    }
}

__global__ __launch_bounds__(256) void aggregate_kernel(
    const float* __restrict__ vmat, int vstride,
    const int* __restrict__ rowidx,
    const int* __restrict__ offsets, const int* __restrict__ perm,
    const float* __restrict__ expw, const float* __restrict__ segsum,
    float* __restrict__ out, int nseg)
{
    __shared__ int   sh_r[128];
    __shared__ float sh_w[128];
    const int s = blockIdx.x;
    if (s >= nseg) return;
    const int d = threadIdx.x;
    const int beg = offsets[s];
    const int end = offsets[s + 1];
    float acc = 0.f;
    for (int cb = beg; cb < end; cb += 128) {
        const int m = min(128, end - cb);
        if (d < m) {
            const int nz = perm[cb + d];
            sh_w[d] = expw[nz];
            sh_r[d] = rowidx[nz];
        }
        __syncthreads();
        for (int j = 0; j < m; j++)
            acc += sh_w[j] * vmat[(size_t)sh_r[j] * vstride + d];
        __syncthreads();
    }
    const float denom = fmaxf(segsum[s], 1e-20f);
    out[(size_t)s * 256 + d] = fmaxf(acc / denom, 0.f);
}

// ---------------------------------------------------------------------------
// Launch
// ---------------------------------------------------------------------------
extern "C" void kernel_launch(void* const* d_in, const int* in_sizes, int n_in,
                              void* d_out, int out_size)
{
    const float* vfeat    = (const float*)d_in[0];
    const float* efeat    = (const float*)d_in[1];
    const int*   node_idx = (const int*)d_in[2];
    const int*   edge_idx = (const int*)d_in[3];
    const float* W_vtx = (const float*)d_in[4];  const float* b_vtx = (const float*)d_in[5];
    const float* W_qe  = (const float*)d_in[6];  const float* b_qe  = (const float*)d_in[7];
    const float* W_kv  = (const float*)d_in[8];  const float* b_kv  = (const float*)d_in[9];
    const float* W_vv  = (const float*)d_in[10]; const float* b_vv  = (const float*)d_in[11];
    const float* W_qv  = (const float*)d_in[12]; const float* b_qv  = (const float*)d_in[13];
    const float* W_ke  = (const float*)d_in[14]; const float* b_ke  = (const float*)d_in[15];
    const float* W_ve  = (const float*)d_in[16]; const float* b_ve  = (const float*)d_in[17];

    float* out_v = (float*)d_out;
    float* out_e = out_v + (size_t)N_NODES * VDIM;

    float *fused1, *fused2, *q1, *Wcomb, *bcomb, *Wcat2, *bcat2;
    float *score, *expw, *segmax, *segsum;
    int *counts, *offsets, *cursor, *perm, *partials;
    cudaGetSymbolAddress((void**)&fused1, g_fused1);
    cudaGetSymbolAddress((void**)&fused2, g_fused2);
    cudaGetSymbolAddress((void**)&q1, g_q1);
    cudaGetSymbolAddress((void**)&Wcomb, g_Wcomb);
    cudaGetSymbolAddress((void**)&bcomb, g_bcomb);
    cudaGetSymbolAddress((void**)&Wcat2, g_Wcat2);
    cudaGetSymbolAddress((void**)&bcat2, g_bcat2);
    cudaGetSymbolAddress((void**)&score, g_score);
    cudaGetSymbolAddress((void**)&expw, g_expw);
    cudaGetSymbolAddress((void**)&segmax, g_segmax);
    cudaGetSymbolAddress((void**)&segsum, g_segsum);
    cudaGetSymbolAddress((void**)&counts, g_counts);
    cudaGetSymbolAddress((void**)&offsets, g_offsets);
    cudaGetSymbolAddress((void**)&cursor, g_cursor);
    cudaGetSymbolAddress((void**)&perm, g_perm);
    cudaGetSymbolAddress((void**)&partials, g_partials);

    const int scoreBlocks = (NNZ * 32 + 255) / 256;
    const int nnzBlocks   = (NNZ + 255) / 256;

    // ---- weight pre-combination (eliminates the feat_v GEMM) ----
    combine_w_kernel<<<F1W / 8, 256>>>(W_kv, W_vv, W_qv, W_vtx, Wcomb);
    combine_b_kernel<<<2, 256>>>(W_kv, W_vv, W_qv, b_kv, b_vv, b_qv, b_vtx, bcomb);

    // ---- concat k2|v2 weights (D2D copies, capture-legal) ----
    cudaMemcpyAsync(Wcat2,             W_ke, (size_t)QDIM * EDIM * 4, cudaMemcpyDeviceToDevice);
    cudaMemcpyAsync(Wcat2 + 128 * 256, W_ve, (size_t)VDIM * EDIM * 4, cudaMemcpyDeviceToDevice);
    cudaMemcpyAsync(bcat2,       b_ke, QDIM * 4, cudaMemcpyDeviceToDevice);
    cudaMemcpyAsync(bcat2 + 128, b_ve, VDIM * 4, cudaMemcpyDeviceToDevice);

    // ---- projections ----
    run_gemm(vfeat, Wcomb, bcomb, fused1, N_NODES, F1W,  KIN);   // k1|v1|q2 directly
    run_gemm(efeat, W_qe,  b_qe,  q1,     N_EDGES, QDIM, KIN);   // q1

    // ---- pass 1: nodes -> hyperedges (seg = edge_idx, nseg = N_EDGES) ----
    {
        const int nseg = N_EDGES;
        const int nb = (nseg + 1023) / 1024;
        init_pass_kernel<<<(nseg + 255) / 256, 256>>>(segmax, segsum, counts, nseg);
        score_kernel<<<scoreBlocks, 256>>>(fused1, F1W, q1, QDIM,
                                           node_idx, edge_idx, edge_idx,
                                           score, segmax, counts, NNZ);
        scan_block_kernel<<<nb, 1024>>>(counts, offsets, partials, nseg);
        scan_partials_kernel<<<1, 64>>>(partials, offsets, nb, nseg);
        scan_add_kernel<<<(nseg + 255) / 256, 256>>>(offsets, cursor, partials, nseg);
        expsum_perm_kernel<<<nnzBlocks, 256>>>(score, edge_idx, segmax, expw, segsum,
                                               cursor, perm, NNZ);
        aggregate_kernel<<<nseg, 256>>>(fused1 + 128, F1W, node_idx, offsets, perm,
                                        expw, segsum, out_e, nseg);   // feat_e
    }

    // ---- edge-side fused projection ----
    run_gemm(out_e, Wcat2, bcat2, fused2, N_EDGES, F2W, EDIM);        // k2|v2

    // ---- pass 2: hyperedges -> nodes (seg = node_idx, nseg = N_NODES) ----
    {
        const int nseg = N_NODES;
        const int nb = (nseg + 1023) / 1024;
        init_pass_kernel<<<(nseg + 255) / 256, 256>>>(segmax, segsum, counts, nseg);
        score_kernel<<<scoreBlocks, 256>>>(fused2, F2W, fused1 + 384, F1W,
                                           edge_idx, node_idx, node_idx,
                                           score, segmax, counts, NNZ);
        scan_block_kernel<<<nb, 1024>>>(counts, offsets, partials, nseg);
        scan_partials_kernel<<<1, 64>>>(partials, offsets, nb, nseg);
        scan_add_kernel<<<(nseg + 255) / 256, 256>>>(offsets, cursor, partials, nseg);
        expsum_perm_kernel<<<nnzBlocks, 256>>>(score, node_idx, segmax, expw, segsum,
                                               cursor, perm, NNZ);
        aggregate_kernel<<<nseg, 256>>>(fused2 + 128, F2W, edge_idx, offsets, perm,
                                        expw, segsum, out_v, nseg);   // feat_v_out
    }
}